// round 1
// baseline (speedup 1.0000x reference)
#include <cuda_runtime.h>
#include <math.h>

// Problem constants
#define LQ 4096
#define CDIM 1024
#define NHEADS 16
#define HDIM 64
#define C3 3072

// Scratch (allocation-free rule: device globals)
__device__ float g_qkv[LQ * C3];    // [L, 3C]  col = t*1024 + h*64 + d
__device__ float g_attn[LQ * CDIM]; // [L, C]   col = h*64 + d

// ---------------------------------------------------------------------------
// SGEMM: C[M,N] = A[M,K] @ B[K,N] + bias[N]   (all row-major, fp32)
// BM=128 BN=128 BK=8, 256 threads, 8x8 per-thread micro-tile
// ---------------------------------------------------------------------------
__global__ __launch_bounds__(256, 2)
void sgemm_bias_kernel(const float* __restrict__ A, const float* __restrict__ B,
                       const float* __restrict__ bias, float* __restrict__ Cout,
                       int M, int N, int K)
{
    const int BM = 128, BN = 128, BK = 8;
    __shared__ float As[BK][BM];
    __shared__ float Bs[BK][BN];

    const int block_row = blockIdx.y * BM;
    const int block_col = blockIdx.x * BN;
    const int tid = threadIdx.x;

    // per-thread output tile position
    const int tr = (tid / 16) * 8;   // 0..120
    const int tc = (tid % 16) * 8;   // 0..120

    // load mapping
    const int arow = tid >> 1;            // 0..127
    const int acol = (tid & 1) * 4;       // 0 or 4
    const int brow = tid >> 5;            // 0..7
    const int bcol = (tid & 31) * 4;      // 0..124

    float acc[8][8];
#pragma unroll
    for (int i = 0; i < 8; i++)
#pragma unroll
        for (int j = 0; j < 8; j++) acc[i][j] = 0.f;

    const float* Aptr = A + (size_t)(block_row + arow) * K + acol;
    const float* Bptr = B + (size_t)brow * N + block_col + bcol;

    for (int k0 = 0; k0 < K; k0 += BK) {
        float4 av = *(const float4*)(Aptr + k0);
        As[acol + 0][arow] = av.x;
        As[acol + 1][arow] = av.y;
        As[acol + 2][arow] = av.z;
        As[acol + 3][arow] = av.w;
        float4 bv = *(const float4*)(Bptr + (size_t)k0 * N);
        *(float4*)&Bs[brow][bcol] = bv;
        __syncthreads();

#pragma unroll
        for (int kk = 0; kk < BK; kk++) {
            float4 a0 = *(const float4*)&As[kk][tr];
            float4 a1 = *(const float4*)&As[kk][tr + 4];
            float4 b0 = *(const float4*)&Bs[kk][tc];
            float4 b1 = *(const float4*)&Bs[kk][tc + 4];
            float ra[8] = {a0.x, a0.y, a0.z, a0.w, a1.x, a1.y, a1.z, a1.w};
            float rb[8] = {b0.x, b0.y, b0.z, b0.w, b1.x, b1.y, b1.z, b1.w};
#pragma unroll
            for (int i = 0; i < 8; i++)
#pragma unroll
                for (int j = 0; j < 8; j++)
                    acc[i][j] = fmaf(ra[i], rb[j], acc[i][j]);
        }
        __syncthreads();
    }

#pragma unroll
    for (int i = 0; i < 8; i++) {
        const int row = block_row + tr + i;
#pragma unroll
        for (int j = 0; j < 8; j += 4) {
            const int col = block_col + tc + j;
            float4 v;
            v.x = acc[i][j + 0] + bias[col + 0];
            v.y = acc[i][j + 1] + bias[col + 1];
            v.z = acc[i][j + 2] + bias[col + 2];
            v.w = acc[i][j + 3] + bias[col + 3];
            *(float4*)&Cout[(size_t)row * N + col] = v;
        }
    }
}

// ---------------------------------------------------------------------------
// Flash attention (causal, online softmax), fp32.
// One CTA per (q-tile of 64 rows, head). 256 threads, 4x4 micro-tiles.
// smem: Qs/Ks/Vs/Ps each 64 x 64 padded to stride 65.
// ---------------------------------------------------------------------------
#define FA_STRIDE 65
#define FA_SMEM_FLOATS (4 * 64 * FA_STRIDE)

__global__ __launch_bounds__(256, 3)
void flash_attn_kernel(float* __restrict__ attn_out)
{
    const int h = blockIdx.y;
    const int qt = (int)gridDim.x - 1 - (int)blockIdx.x; // heavy tiles first
    const int tid = threadIdx.x;
    const int tr = tid >> 4;   // 0..15 -> rows tr*4..tr*4+3
    const int tc = tid & 15;   // 0..15 -> cols tc*4..tc*4+3

    extern __shared__ float sm[];
    float* Qs = sm;
    float* Ks = Qs + 64 * FA_STRIDE;
    float* Vs = Ks + 64 * FA_STRIDE;
    float* Ps = Vs + 64 * FA_STRIDE;

    const float* qkv = g_qkv;
    const float scale = 0.125f; // 1/sqrt(64)

    // ---- load Q tile (scaled) ----
#pragma unroll
    for (int r = 0; r < 4; r++) {
        int idx = tid + 256 * r;        // 0..1023 float4 slots
        int row = idx >> 4;             // 0..63
        int col = (idx & 15) * 4;       // 0..60
        float4 qv = *(const float4*)&qkv[(size_t)(qt * 64 + row) * C3 + h * HDIM + col];
        float* dst = &Qs[row * FA_STRIDE + col];
        dst[0] = qv.x * scale; dst[1] = qv.y * scale;
        dst[2] = qv.z * scale; dst[3] = qv.w * scale;
    }

    float m[4], l[4], o[4][4];
#pragma unroll
    for (int i = 0; i < 4; i++) {
        m[i] = -INFINITY; l[i] = 0.f;
#pragma unroll
        for (int j = 0; j < 4; j++) o[i][j] = 0.f;
    }

    const int qrow0 = qt * 64 + tr * 4;

    for (int kt = 0; kt <= qt; kt++) {
        // ---- load K and V tiles ----
#pragma unroll
        for (int r = 0; r < 4; r++) {
            int idx = tid + 256 * r;
            int row = idx >> 4;
            int col = (idx & 15) * 4;
            size_t base = (size_t)(kt * 64 + row) * C3 + h * HDIM + col;
            float4 kv = *(const float4*)&qkv[base + 1024];
            float4 vv = *(const float4*)&qkv[base + 2048];
            float* kd = &Ks[row * FA_STRIDE + col];
            kd[0] = kv.x; kd[1] = kv.y; kd[2] = kv.z; kd[3] = kv.w;
            float* vd = &Vs[row * FA_STRIDE + col];
            vd[0] = vv.x; vd[1] = vv.y; vd[2] = vv.z; vd[3] = vv.w;
        }
        __syncthreads();

        // ---- S = Q @ K^T (4x4 per thread) ----
        float s[4][4];
#pragma unroll
        for (int i = 0; i < 4; i++)
#pragma unroll
            for (int j = 0; j < 4; j++) s[i][j] = 0.f;

#pragma unroll 4
        for (int d = 0; d < 64; d++) {
            float qa[4], kb[4];
#pragma unroll
            for (int i = 0; i < 4; i++) qa[i] = Qs[(tr * 4 + i) * FA_STRIDE + d];
#pragma unroll
            for (int j = 0; j < 4; j++) kb[j] = Ks[(tc * 4 + j) * FA_STRIDE + d];
#pragma unroll
            for (int i = 0; i < 4; i++)
#pragma unroll
                for (int j = 0; j < 4; j++)
                    s[i][j] = fmaf(qa[i], kb[j], s[i][j]);
        }

        // ---- causal mask on diagonal tile ----
        if (kt == qt) {
            const int kcol0 = kt * 64 + tc * 4;
#pragma unroll
            for (int i = 0; i < 4; i++)
#pragma unroll
                for (int j = 0; j < 4; j++)
                    if (kcol0 + j > qrow0 + i) s[i][j] = -INFINITY;
        }

        // ---- online softmax update (row stats across 16-lane groups) ----
#pragma unroll
        for (int i = 0; i < 4; i++) {
            float mt = fmaxf(fmaxf(s[i][0], s[i][1]), fmaxf(s[i][2], s[i][3]));
#pragma unroll
            for (int off = 1; off < 16; off <<= 1)
                mt = fmaxf(mt, __shfl_xor_sync(0xffffffffu, mt, off));
            float mnew = fmaxf(m[i], mt);
            float corr = __expf(m[i] - mnew);  // 0 when m[i] == -inf
            float p0 = __expf(s[i][0] - mnew);
            float p1 = __expf(s[i][1] - mnew);
            float p2 = __expf(s[i][2] - mnew);
            float p3 = __expf(s[i][3] - mnew);
            float psum = (p0 + p1) + (p2 + p3);
#pragma unroll
            for (int off = 1; off < 16; off <<= 1)
                psum += __shfl_xor_sync(0xffffffffu, psum, off);
            l[i] = l[i] * corr + psum;
            m[i] = mnew;
#pragma unroll
            for (int j = 0; j < 4; j++) o[i][j] *= corr;
            float* prow = &Ps[(tr * 4 + i) * FA_STRIDE + tc * 4];
            prow[0] = p0; prow[1] = p1; prow[2] = p2; prow[3] = p3;
        }
        __syncthreads();

        // ---- O += P @ V (4x4 per thread; cols tc*4.. are head dims) ----
#pragma unroll 4
        for (int k = 0; k < 64; k++) {
            float pa[4], vb[4];
#pragma unroll
            for (int i = 0; i < 4; i++) pa[i] = Ps[(tr * 4 + i) * FA_STRIDE + k];
#pragma unroll
            for (int j = 0; j < 4; j++) vb[j] = Vs[k * FA_STRIDE + tc * 4 + j];
#pragma unroll
            for (int i = 0; i < 4; i++)
#pragma unroll
                for (int j = 0; j < 4; j++)
                    o[i][j] = fmaf(pa[i], vb[j], o[i][j]);
        }
        __syncthreads(); // protect Ks/Vs/Ps reuse next iteration
    }

    // ---- epilogue: normalize + write [L, H*D] ----
#pragma unroll
    for (int i = 0; i < 4; i++) {
        float inv = 1.f / l[i];
        const int row = qrow0 + i;
        float* dst = &attn_out[(size_t)row * CDIM + h * HDIM + tc * 4];
#pragma unroll
        for (int j = 0; j < 4; j++) dst[j] = o[i][j] * inv;
    }
}

// ---------------------------------------------------------------------------
// Launch
// ---------------------------------------------------------------------------
extern "C" void kernel_launch(void* const* d_in, const int* in_sizes, int n_in,
                              void* d_out, int out_size)
{
    (void)in_sizes; (void)n_in; (void)out_size;
    const float* x    = (const float*)d_in[0];
    const float* Wqkv = (const float*)d_in[1];
    const float* bqkv = (const float*)d_in[2];
    const float* Wout = (const float*)d_in[3];
    const float* bout = (const float*)d_in[4];
    float* out = (float*)d_out;

    float* qkv_ptr = nullptr;
    float* attn_ptr = nullptr;
    cudaGetSymbolAddress((void**)&qkv_ptr, g_qkv);
    cudaGetSymbolAddress((void**)&attn_ptr, g_attn);

    // 1) QKV projection: [4096,1024] @ [1024,3072] + bias
    {
        dim3 grid(C3 / 128, LQ / 128);
        sgemm_bias_kernel<<<grid, 256>>>(x, Wqkv, bqkv, qkv_ptr, LQ, C3, CDIM);
    }

    // 2) Causal flash attention
    {
        static int smem_set = 0;
        size_t smem = FA_SMEM_FLOATS * sizeof(float); // 66,560 B
        if (!smem_set) {
            cudaFuncSetAttribute(flash_attn_kernel,
                                 cudaFuncAttributeMaxDynamicSharedMemorySize,
                                 (int)smem);
            smem_set = 1;
        }
        dim3 grid(LQ / 64, NHEADS);
        flash_attn_kernel<<<grid, 256, smem>>>(attn_ptr);
    }

    // 3) Output projection: [4096,1024] @ [1024,1024] + bias
    {
        dim3 grid(CDIM / 128, LQ / 128);
        sgemm_bias_kernel<<<grid, 256>>>(attn_ptr, Wout, bout, out, LQ, CDIM, CDIM);
    }
}

// round 3
// speedup vs baseline: 2.9595x; 2.9595x over previous
#include <cuda_runtime.h>
#include <cuda_bf16.h>
#include <math.h>
#include <stdint.h>

// Problem constants
#define LQ 4096
#define CDIM 1024
#define NHEADS 16
#define HDIM 64
#define C3 3072
// 0.125 * log2(e): fold softmax base-2 conversion into Q scaling
#define QSCALE 0.18033688011112042f

// ---------------------------------------------------------------------------
// Device-global scratch (allocation-free rule)
// ---------------------------------------------------------------------------
__device__ float g_qkv[LQ * C3];
__device__ float g_attn[LQ * CDIM];
__device__ __nv_bfloat16 g_xh[LQ * CDIM], g_xl[LQ * CDIM];
__device__ __nv_bfloat16 g_ah[LQ * CDIM], g_al[LQ * CDIM];
__device__ __nv_bfloat16 g_wqh[C3 * CDIM], g_wql[C3 * CDIM];     // [N][K]
__device__ __nv_bfloat16 g_woh[CDIM * CDIM], g_wol[CDIM * CDIM]; // [N][K]
__device__ __nv_bfloat16 g_qh[NHEADS * LQ * HDIM], g_ql[NHEADS * LQ * HDIM];
__device__ __nv_bfloat16 g_kh[NHEADS * LQ * HDIM], g_kl[NHEADS * LQ * HDIM];
__device__ __nv_bfloat16 g_vh[NHEADS * LQ * HDIM], g_vl[NHEADS * LQ * HDIM];

// ---------------------------------------------------------------------------
// Warp-MMA helpers (sm_80-era PTX: works on baseline compute_103)
// ---------------------------------------------------------------------------
__device__ __forceinline__ void mma16816(float* c, uint32_t a0, uint32_t a1,
                                         uint32_t a2, uint32_t a3,
                                         uint32_t b0, uint32_t b1) {
    asm volatile(
        "mma.sync.aligned.m16n8k16.row.col.f32.bf16.bf16.f32 "
        "{%0,%1,%2,%3}, {%4,%5,%6,%7}, {%8,%9}, {%0,%1,%2,%3};"
        : "+f"(c[0]), "+f"(c[1]), "+f"(c[2]), "+f"(c[3])
        : "r"(a0), "r"(a1), "r"(a2), "r"(a3), "r"(b0), "r"(b1));
}

__device__ __forceinline__ void ldsm4(uint32_t* r, uint32_t addr) {
    asm volatile("ldmatrix.sync.aligned.m8n8.x4.shared.b16 {%0,%1,%2,%3}, [%4];"
                 : "=r"(r[0]), "=r"(r[1]), "=r"(r[2]), "=r"(r[3]) : "r"(addr));
}
__device__ __forceinline__ void ldsm4t(uint32_t* r, uint32_t addr) {
    asm volatile("ldmatrix.sync.aligned.m8n8.x4.trans.shared.b16 {%0,%1,%2,%3}, [%4];"
                 : "=r"(r[0]), "=r"(r[1]), "=r"(r[2]), "=r"(r[3]) : "r"(addr));
}

#define CPA(s, g) \
    asm volatile("cp.async.cg.shared.global [%0], [%1], 16;" :: "r"(s), "l"(g) : "memory")
#define CPC() asm volatile("cp.async.commit_group;" ::: "memory")
#define CPW(n) asm volatile("cp.async.wait_group %0;" :: "n"(n) : "memory")

__device__ __forceinline__ float ex2f(float x) {
    float y;
    asm("ex2.approx.f32 %0, %1;" : "=f"(y) : "f"(x));
    return y;
}

__device__ __forceinline__ uint32_t packbf(float a, float b) {
    __nv_bfloat162 t = __floats2bfloat162_rn(a, b); // .x = a (low half)
    return *(uint32_t*)&t;
}
__device__ __forceinline__ float lowres(float a) {
    return a - __bfloat162float(__float2bfloat16(a));
}

// ---------------------------------------------------------------------------
// Prep kernels
// ---------------------------------------------------------------------------
__global__ void split_kernel(const float* __restrict__ s,
                             __nv_bfloat16* __restrict__ h,
                             __nv_bfloat16* __restrict__ l, int n) {
    int i = blockIdx.x * blockDim.x + threadIdx.x;
    if (i < n) {
        float v = s[i];
        __nv_bfloat16 vh = __float2bfloat16(v);
        h[i] = vh;
        l[i] = __float2bfloat16(v - __bfloat162float(vh));
    }
}

// W [K][N] f32 -> Th/Tl [N][K] bf16
__global__ void tsplit_kernel(const float* __restrict__ W,
                              __nv_bfloat16* __restrict__ Th,
                              __nv_bfloat16* __restrict__ Tl, int K, int N) {
    __shared__ float t[32][33];
    int n0 = blockIdx.x * 32, k0 = blockIdx.y * 32;
    int tx = threadIdx.x & 31, ty = threadIdx.x >> 5;
#pragma unroll
    for (int r = 0; r < 32; r += 8)
        t[ty + r][tx] = W[(size_t)(k0 + ty + r) * N + n0 + tx];
    __syncthreads();
#pragma unroll
    for (int r = 0; r < 32; r += 8) {
        float v = t[tx][ty + r];
        int n = n0 + ty + r, k = k0 + tx;
        __nv_bfloat16 vh = __float2bfloat16(v);
        Th[(size_t)n * K + k] = vh;
        Tl[(size_t)n * K + k] = __float2bfloat16(v - __bfloat162float(vh));
    }
}

// g_qkv [L][3C] -> per-head bf16 hi/lo Q(scaled)/K/V, layout [H][L][64]
__global__ void qkvprep_kernel() {
    int idx = blockIdx.x * 256 + threadIdx.x; // L*1024 total
    int l = idx >> 10, c = idx & 1023;
    int h = c >> 6, d = c & 63;
    const float* row = g_qkv + (size_t)l * C3;
    float q = row[c] * QSCALE;
    float k = row[1024 + c];
    float v = row[2048 + c];
    size_t o = ((size_t)h * LQ + l) * 64 + d;
    __nv_bfloat16 qb = __float2bfloat16(q);
    g_qh[o] = qb; g_ql[o] = __float2bfloat16(q - __bfloat162float(qb));
    __nv_bfloat16 kb = __float2bfloat16(k);
    g_kh[o] = kb; g_kl[o] = __float2bfloat16(k - __bfloat162float(kb));
    __nv_bfloat16 vb = __float2bfloat16(v);
    g_vh[o] = vb; g_vl[o] = __float2bfloat16(v - __bfloat162float(vb));
}

// ---------------------------------------------------------------------------
// HMMA split-bf16 GEMM: C[M,N] = (Ah+Al)[M,K] @ (Bh+Bl)^T[N,K] + bias
// (3 passes: hh, hl, lh). BM=BN=128, BK=32, 256 threads, warps 4m x 2n.
// ---------------------------------------------------------------------------
__global__ __launch_bounds__(256)
void gemm_mma(const __nv_bfloat16* __restrict__ Ah,
              const __nv_bfloat16* __restrict__ Al,
              const __nv_bfloat16* __restrict__ Bh,
              const __nv_bfloat16* __restrict__ Bl,
              const float* __restrict__ bias,
              float* __restrict__ C, int M, int N, int K) {
    __shared__ __align__(16) __nv_bfloat16 sA[2][128 * 40];
    __shared__ __align__(16) __nv_bfloat16 sB[2][128 * 40];
    const int tid = threadIdx.x, lane = tid & 31, wid = tid >> 5;
    const int wm = wid >> 1, wn = wid & 1;
    const int m0 = blockIdx.y * 128, n0 = blockIdx.x * 128;
    const uint32_t uA = (uint32_t)__cvta_generic_to_shared(sA);
    const uint32_t uB = (uint32_t)__cvta_generic_to_shared(sB);

    float acc[2][8][4] = {};

    const int kch = K >> 5;
    const int nit = 3 * kch;

    auto issue = [&](int it) {
        int p = it / kch;
        int kk = (it - p * kch) << 5;
        const __nv_bfloat16* Aop = (p < 2) ? Ah : Al;
        const __nv_bfloat16* Bop = (p == 1) ? Bl : Bh;
        int b = it & 1;
#pragma unroll
        for (int r = 0; r < 2; r++) {
            int slot = tid + (r << 8);
            int row = slot >> 2, c = slot & 3;
            uint32_t so = (uint32_t)((row * 40 + c * 8) * 2) + b * 10240;
            CPA(uA + so, Aop + (size_t)(m0 + row) * K + kk + c * 8);
            CPA(uB + so, Bop + (size_t)(n0 + row) * K + kk + c * 8);
        }
        CPC();
    };

    issue(0);
    for (int it = 0; it < nit; ++it) {
        if (it + 1 < nit) { issue(it + 1); CPW(1); }
        else             { CPW(0); }
        __syncthreads();
        const uint32_t bA = uA + (it & 1) * 10240;
        const uint32_t bB = uB + (it & 1) * 10240;
#pragma unroll
        for (int ks = 0; ks < 2; ks++) {
            uint32_t af[2][4];
#pragma unroll
            for (int mt = 0; mt < 2; mt++) {
                int row = wm * 32 + mt * 16 + (lane & 15);
                int col = ks * 16 + ((lane >> 4) << 3);
                ldsm4(af[mt], bA + (row * 40 + col) * 2);
            }
#pragma unroll
            for (int np = 0; np < 4; np++) {
                uint32_t b4[4];
                int n = wn * 64 + np * 16 + ((lane >> 4) << 3) + (lane & 7);
                int k = ks * 16 + (((lane >> 3) & 1) << 3);
                ldsm4(b4, bB + (n * 40 + k) * 2);
#pragma unroll
                for (int mt = 0; mt < 2; mt++) {
                    mma16816(acc[mt][2 * np], af[mt][0], af[mt][1], af[mt][2], af[mt][3], b4[0], b4[1]);
                    mma16816(acc[mt][2 * np + 1], af[mt][0], af[mt][1], af[mt][2], af[mt][3], b4[2], b4[3]);
                }
            }
        }
        __syncthreads();
    }

#pragma unroll
    for (int mt = 0; mt < 2; mt++) {
        int r0 = m0 + wm * 32 + mt * 16 + (lane >> 2);
#pragma unroll
        for (int nt = 0; nt < 8; nt++) {
            int c = n0 + wn * 64 + nt * 8 + ((lane & 3) << 1);
            float b0 = bias[c], b1 = bias[c + 1];
            float2 v0 = make_float2(acc[mt][nt][0] + b0, acc[mt][nt][1] + b1);
            float2 v1 = make_float2(acc[mt][nt][2] + b0, acc[mt][nt][3] + b1);
            *(float2*)&C[(size_t)r0 * N + c] = v0;
            *(float2*)&C[(size_t)(r0 + 8) * N + c] = v1;
        }
    }
}

// ---------------------------------------------------------------------------
// HMMA flash attention (causal, online softmax in base-2 domain).
// CTA = 128 threads (4 warps x 16 q-rows = 64-row q-tile) per head.
// K/V tiles 64x64 bf16 hi/lo in smem (stride 72 bf16 = conflict-free).
// S = (Q*scale) K^T and O += P V, each via 3 split-bf16 passes.
// ---------------------------------------------------------------------------
#define AT_ST 72
#define AT_TILE (64 * AT_ST * 2)   // 9216 bytes per tile
#define AT_SMEM (4 * AT_TILE)      // Kh, Kl, Vh, Vl

__global__ __launch_bounds__(128)
void flash_mma(float* __restrict__ Out) {
    const int h = blockIdx.y;
    const int qt = (int)gridDim.x - 1 - (int)blockIdx.x; // heavy tiles first
    const int tid = threadIdx.x, lane = tid & 31, wid = tid >> 5;
    extern __shared__ char sm[];
    const uint32_t u0 = (uint32_t)__cvta_generic_to_shared(sm);
    const uint32_t uKh = u0, uKl = u0 + AT_TILE, uVh = u0 + 2 * AT_TILE,
                   uVl = u0 + 3 * AT_TILE;
    const size_t hbase = (size_t)h * LQ * HDIM;

    // ---- stage Q hi/lo (into K buffers), extract fragments ----
#pragma unroll
    for (int r = 0; r < 4; r++) {
        int slot = tid + (r << 7);
        int row = slot >> 3, c = slot & 7;
        size_t g = hbase + (size_t)(qt * 64 + row) * 64 + c * 8;
        uint32_t so = row * (AT_ST * 2) + c * 16;
        CPA(uKh + so, g_qh + g);
        CPA(uKl + so, g_ql + g);
    }
    CPC(); CPW(0); __syncthreads();

    uint32_t qh[4][4], ql[4][4];
#pragma unroll
    for (int ks = 0; ks < 4; ks++) {
        int row = wid * 16 + (lane & 15);
        int col = ks * 16 + ((lane >> 4) << 3);
        ldsm4(qh[ks], uKh + (row * AT_ST + col) * 2);
        ldsm4(ql[ks], uKl + (row * AT_ST + col) * 2);
    }

    float o[8][4] = {};
    float m0 = -1e30f, m1 = -1e30f, l0 = 0.f, l1 = 0.f;
    const int grow0 = qt * 64 + wid * 16 + (lane >> 2);

    for (int kt = 0; kt <= qt; ++kt) {
        __syncthreads(); // previous compute (or Q extraction) done before overwrite
#pragma unroll
        for (int r = 0; r < 4; r++) {
            int slot = tid + (r << 7);
            int row = slot >> 3, c = slot & 7;
            size_t g = hbase + (size_t)(kt * 64 + row) * 64 + c * 8;
            uint32_t so = row * (AT_ST * 2) + c * 16;
            CPA(uKh + so, g_kh + g);
            CPA(uKl + so, g_kl + g);
            CPA(uVh + so, g_vh + g);
            CPA(uVl + so, g_vl + g);
        }
        CPC(); CPW(0); __syncthreads();

        // ---- S = Q K^T (3 passes) ----
        float s[8][4] = {};
#pragma unroll
        for (int pass = 0; pass < 3; ++pass) {
            const uint32_t(*qa)[4] = (pass < 2) ? qh : ql;
            const uint32_t kb = (pass == 1) ? uKl : uKh;
#pragma unroll
            for (int ks = 0; ks < 4; ks++) {
#pragma unroll
                for (int np = 0; np < 4; np++) {
                    uint32_t b4[4];
                    int n = np * 16 + ((lane >> 4) << 3) + (lane & 7);
                    int k = ks * 16 + (((lane >> 3) & 1) << 3);
                    ldsm4(b4, kb + (n * AT_ST + k) * 2);
                    mma16816(s[2 * np], qa[ks][0], qa[ks][1], qa[ks][2], qa[ks][3], b4[0], b4[1]);
                    mma16816(s[2 * np + 1], qa[ks][0], qa[ks][1], qa[ks][2], qa[ks][3], b4[2], b4[3]);
                }
            }
        }

        // ---- causal mask on the diagonal tile ----
        if (kt == qt) {
#pragma unroll
            for (int nt = 0; nt < 8; nt++) {
                int c0 = kt * 64 + nt * 8 + ((lane & 3) << 1);
                if (c0 > grow0) s[nt][0] = -1e30f;
                if (c0 + 1 > grow0) s[nt][1] = -1e30f;
                if (c0 > grow0 + 8) s[nt][2] = -1e30f;
                if (c0 + 1 > grow0 + 8) s[nt][3] = -1e30f;
            }
        }

        // ---- online softmax (base-2; rows grow0 / grow0+8) ----
        float mx0 = -1e30f, mx1 = -1e30f;
#pragma unroll
        for (int nt = 0; nt < 8; nt++) {
            mx0 = fmaxf(mx0, fmaxf(s[nt][0], s[nt][1]));
            mx1 = fmaxf(mx1, fmaxf(s[nt][2], s[nt][3]));
        }
        mx0 = fmaxf(mx0, __shfl_xor_sync(0xffffffffu, mx0, 1));
        mx0 = fmaxf(mx0, __shfl_xor_sync(0xffffffffu, mx0, 2));
        mx1 = fmaxf(mx1, __shfl_xor_sync(0xffffffffu, mx1, 1));
        mx1 = fmaxf(mx1, __shfl_xor_sync(0xffffffffu, mx1, 2));
        float mn0 = fmaxf(m0, mx0), mn1 = fmaxf(m1, mx1);
        float corr0 = ex2f(m0 - mn0), corr1 = ex2f(m1 - mn1);
        m0 = mn0; m1 = mn1;
        float ps0 = 0.f, ps1 = 0.f;
#pragma unroll
        for (int nt = 0; nt < 8; nt++) {
            s[nt][0] = ex2f(s[nt][0] - mn0);
            s[nt][1] = ex2f(s[nt][1] - mn0);
            s[nt][2] = ex2f(s[nt][2] - mn1);
            s[nt][3] = ex2f(s[nt][3] - mn1);
            ps0 += s[nt][0] + s[nt][1];
            ps1 += s[nt][2] + s[nt][3];
        }
        ps0 += __shfl_xor_sync(0xffffffffu, ps0, 1);
        ps0 += __shfl_xor_sync(0xffffffffu, ps0, 2);
        ps1 += __shfl_xor_sync(0xffffffffu, ps1, 1);
        ps1 += __shfl_xor_sync(0xffffffffu, ps1, 2);
        l0 = l0 * corr0 + ps0;
        l1 = l1 * corr1 + ps1;
#pragma unroll
        for (int nt = 0; nt < 8; nt++) {
            o[nt][0] *= corr0; o[nt][1] *= corr0;
            o[nt][2] *= corr1; o[nt][3] *= corr1;
        }

        // ---- O += P V (3 passes; P fragments re-packed from s regs) ----
#pragma unroll
        for (int pass = 0; pass < 3; ++pass) {
            const uint32_t vb = (pass == 1) ? uVl : uVh;
#pragma unroll
            for (int ks = 0; ks < 4; ks++) {
                uint32_t a0, a1, a2, a3;
                if (pass < 2) {
                    a0 = packbf(s[2 * ks][0], s[2 * ks][1]);
                    a1 = packbf(s[2 * ks][2], s[2 * ks][3]);
                    a2 = packbf(s[2 * ks + 1][0], s[2 * ks + 1][1]);
                    a3 = packbf(s[2 * ks + 1][2], s[2 * ks + 1][3]);
                } else {
                    a0 = packbf(lowres(s[2 * ks][0]), lowres(s[2 * ks][1]));
                    a1 = packbf(lowres(s[2 * ks][2]), lowres(s[2 * ks][3]));
                    a2 = packbf(lowres(s[2 * ks + 1][0]), lowres(s[2 * ks + 1][1]));
                    a3 = packbf(lowres(s[2 * ks + 1][2]), lowres(s[2 * ks + 1][3]));
                }
#pragma unroll
                for (int np = 0; np < 4; np++) {
                    uint32_t b4[4];
                    int row = ks * 16 + ((lane >> 3) & 1) * 8 + (lane & 7);
                    int dc = np * 16 + ((lane >> 4) << 3);
                    ldsm4t(b4, vb + (row * AT_ST + dc) * 2);
                    mma16816(o[2 * np], a0, a1, a2, a3, b4[0], b4[1]);
                    mma16816(o[2 * np + 1], a0, a1, a2, a3, b4[2], b4[3]);
                }
            }
        }
    }

    // ---- epilogue ----
    float inv0 = 1.f / l0, inv1 = 1.f / l1;
#pragma unroll
    for (int nt = 0; nt < 8; nt++) {
        int c = h * 64 + nt * 8 + ((lane & 3) << 1);
        float2 v0 = make_float2(o[nt][0] * inv0, o[nt][1] * inv0);
        float2 v1 = make_float2(o[nt][2] * inv1, o[nt][3] * inv1);
        *(float2*)&Out[(size_t)grow0 * CDIM + c] = v0;
        *(float2*)&Out[(size_t)(grow0 + 8) * CDIM + c] = v1;
    }
}

// ---------------------------------------------------------------------------
// Launch
// ---------------------------------------------------------------------------
extern "C" void kernel_launch(void* const* d_in, const int* in_sizes, int n_in,
                              void* d_out, int out_size) {
    (void)in_sizes; (void)n_in; (void)out_size;
    const float* x = (const float*)d_in[0];
    const float* Wqkv = (const float*)d_in[1];
    const float* bqkv = (const float*)d_in[2];
    const float* Wout = (const float*)d_in[3];
    const float* bout = (const float*)d_in[4];
    float* out = (float*)d_out;

    float *qkv_ptr, *attn_ptr;
    __nv_bfloat16 *xh, *xl, *ah, *al, *wqh, *wql, *woh, *wol;
    cudaGetSymbolAddress((void**)&qkv_ptr, g_qkv);
    cudaGetSymbolAddress((void**)&attn_ptr, g_attn);
    cudaGetSymbolAddress((void**)&xh, g_xh);
    cudaGetSymbolAddress((void**)&xl, g_xl);
    cudaGetSymbolAddress((void**)&ah, g_ah);
    cudaGetSymbolAddress((void**)&al, g_al);
    cudaGetSymbolAddress((void**)&wqh, g_wqh);
    cudaGetSymbolAddress((void**)&wql, g_wql);
    cudaGetSymbolAddress((void**)&woh, g_woh);
    cudaGetSymbolAddress((void**)&wol, g_wol);

    // prep
    split_kernel<<<(LQ * CDIM) / 256, 256>>>(x, xh, xl, LQ * CDIM);
    tsplit_kernel<<<dim3(C3 / 32, CDIM / 32), 256>>>(Wqkv, wqh, wql, CDIM, C3);
    tsplit_kernel<<<dim3(CDIM / 32, CDIM / 32), 256>>>(Wout, woh, wol, CDIM, CDIM);

    // 1) QKV projection
    gemm_mma<<<dim3(C3 / 128, LQ / 128), 256>>>(xh, xl, wqh, wql, bqkv,
                                                qkv_ptr, LQ, C3, CDIM);

    // 2) reshape to per-head bf16 hi/lo
    qkvprep_kernel<<<(LQ * CDIM) / 256, 256>>>();

    // 3) causal flash attention (HMMA)
    flash_mma<<<dim3(LQ / 64, NHEADS), 128, AT_SMEM>>>(attn_ptr);

    // 4) output projection
    split_kernel<<<(LQ * CDIM) / 256, 256>>>(attn_ptr, ah, al, LQ * CDIM);
    gemm_mma<<<dim3(CDIM / 128, LQ / 128), 256>>>(ah, al, woh, wol, bout,
                                                  out, LQ, CDIM, CDIM);
}

// round 5
// speedup vs baseline: 3.4456x; 1.1643x over previous
#include <cuda_runtime.h>
#include <cuda_bf16.h>
#include <math.h>
#include <stdint.h>

#define LQ 4096
#define CDIM 1024
#define NHEADS 16
#define HDIM 64
#define C3 3072
// 0.125 * log2(e): fold softmax base-2 conversion into Q scaling
#define QSCALE 0.18033688011112042f

// ---------------------------------------------------------------------------
// Device-global scratch
// ---------------------------------------------------------------------------
__device__ __nv_bfloat16 g_xh[LQ * CDIM], g_xl[LQ * CDIM];
__device__ __nv_bfloat16 g_ah[LQ * CDIM], g_al[LQ * CDIM];
__device__ __nv_bfloat16 g_wqh[C3 * CDIM], g_wql[C3 * CDIM];     // [N][K]
__device__ __nv_bfloat16 g_woh[CDIM * CDIM], g_wol[CDIM * CDIM]; // [N][K]
__device__ __nv_bfloat16 g_qh[NHEADS * LQ * HDIM], g_ql[NHEADS * LQ * HDIM];
__device__ __nv_bfloat16 g_kh[NHEADS * LQ * HDIM], g_kl[NHEADS * LQ * HDIM];
__device__ __nv_bfloat16 g_vh[NHEADS * LQ * HDIM], g_vl[NHEADS * LQ * HDIM];

// ---------------------------------------------------------------------------
// Warp-MMA helpers
// ---------------------------------------------------------------------------
__device__ __forceinline__ void mma16816(float* c, const uint32_t* a,
                                         uint32_t b0, uint32_t b1) {
    asm volatile(
        "mma.sync.aligned.m16n8k16.row.col.f32.bf16.bf16.f32 "
        "{%0,%1,%2,%3}, {%4,%5,%6,%7}, {%8,%9}, {%0,%1,%2,%3};"
        : "+f"(c[0]), "+f"(c[1]), "+f"(c[2]), "+f"(c[3])
        : "r"(a[0]), "r"(a[1]), "r"(a[2]), "r"(a[3]), "r"(b0), "r"(b1));
}
__device__ __forceinline__ void ldsm4(uint32_t* r, uint32_t addr) {
    asm volatile("ldmatrix.sync.aligned.m8n8.x4.shared.b16 {%0,%1,%2,%3}, [%4];"
                 : "=r"(r[0]), "=r"(r[1]), "=r"(r[2]), "=r"(r[3]) : "r"(addr));
}
__device__ __forceinline__ void ldsm4t(uint32_t* r, uint32_t addr) {
    asm volatile("ldmatrix.sync.aligned.m8n8.x4.trans.shared.b16 {%0,%1,%2,%3}, [%4];"
                 : "=r"(r[0]), "=r"(r[1]), "=r"(r[2]), "=r"(r[3]) : "r"(addr));
}
#define CPA(s, g) \
    asm volatile("cp.async.cg.shared.global [%0], [%1], 16;" :: "r"(s), "l"(g) : "memory")
#define CPC() asm volatile("cp.async.commit_group;" ::: "memory")
#define CPW0() asm volatile("cp.async.wait_group 0;" ::: "memory")

__device__ __forceinline__ float ex2f(float x) {
    float y; asm("ex2.approx.f32 %0, %1;" : "=f"(y) : "f"(x)); return y;
}
__device__ __forceinline__ uint32_t packbf(float a, float b) {
    __nv_bfloat162 t = __floats2bfloat162_rn(a, b);
    return *(uint32_t*)&t;
}
__device__ __forceinline__ float lowres(float a) {
    return a - __bfloat162float(__float2bfloat16(a));
}
__device__ __forceinline__ void split2(float a, float b,
                                       __nv_bfloat162& hi, __nv_bfloat162& lo) {
    __nv_bfloat16 ah = __float2bfloat16(a), bh = __float2bfloat16(b);
    hi.x = ah; hi.y = bh;
    lo.x = __float2bfloat16(a - __bfloat162float(ah));
    lo.y = __float2bfloat16(b - __bfloat162float(bh));
}

// ---------------------------------------------------------------------------
// Prep kernels
// ---------------------------------------------------------------------------
__global__ void split_kernel(const float* __restrict__ s,
                             __nv_bfloat16* __restrict__ h,
                             __nv_bfloat16* __restrict__ l, int n) {
    int i = blockIdx.x * blockDim.x + threadIdx.x;
    if (i < n) {
        float v = s[i];
        __nv_bfloat16 vh = __float2bfloat16(v);
        h[i] = vh;
        l[i] = __float2bfloat16(v - __bfloat162float(vh));
    }
}
// W [K][N] f32 -> Th/Tl [N][K] bf16
__global__ void tsplit_kernel(const float* __restrict__ W,
                              __nv_bfloat16* __restrict__ Th,
                              __nv_bfloat16* __restrict__ Tl, int K, int N) {
    __shared__ float t[32][33];
    int n0 = blockIdx.x * 32, k0 = blockIdx.y * 32;
    int tx = threadIdx.x & 31, ty = threadIdx.x >> 5;
#pragma unroll
    for (int r = 0; r < 32; r += 8)
        t[ty + r][tx] = W[(size_t)(k0 + ty + r) * N + n0 + tx];
    __syncthreads();
#pragma unroll
    for (int r = 0; r < 32; r += 8) {
        float v = t[tx][ty + r];
        int n = n0 + ty + r, k = k0 + tx;
        __nv_bfloat16 vh = __float2bfloat16(v);
        Th[(size_t)n * K + k] = vh;
        Tl[(size_t)n * K + k] = __float2bfloat16(v - __bfloat162float(vh));
    }
}

// ---------------------------------------------------------------------------
// Interleaved split-bf16 HMMA GEMM.
// C = (Ah+Al)[M,K] @ (Bh+Bl)^T[N,K] + bias  via hh+hl+lh in ONE K sweep.
// BM=BN=128, BK=32. Per stage: Ah|Al|Bh|Bl tiles (128x32 each, stride 40).
// 2-stage cp.async pipeline, single __syncthreads per chunk.
// MODE 0: f32 out with bias.  MODE 1: fused QKV epilogue -> per-head bf16
// hi/lo Q(scaled)/K/V in [H][L][64] layout.
// ---------------------------------------------------------------------------
#define G_TILE 10240        // 128 * 40 * 2 bytes
#define G_STAGE (4 * G_TILE)
#define G_SMEM (2 * G_STAGE)

template <int MODE>
__global__ __launch_bounds__(256)
void gemm3(const __nv_bfloat16* __restrict__ Ah,
           const __nv_bfloat16* __restrict__ Al,
           const __nv_bfloat16* __restrict__ Bh,
           const __nv_bfloat16* __restrict__ Bl,
           const float* __restrict__ bias,
           float* __restrict__ C, int M, int N, int K) {
    extern __shared__ __align__(16) char dsm[];
    const uint32_t uS = (uint32_t)__cvta_generic_to_shared(dsm);
    const int tid = threadIdx.x, lane = tid & 31, wid = tid >> 5;
    const int wm = wid >> 1, wn = wid & 1;
    const int m0 = blockIdx.y * 128, n0 = blockIdx.x * 128;

    float acc[2][8][4] = {};
    const int kch = K >> 5;

    auto issue = [&](int chunk) {
        const int kk = chunk << 5;
        const uint32_t sb = uS + (chunk & 1) * G_STAGE;
#pragma unroll
        for (int r = 0; r < 8; r++) {
            const int t = r >> 1;                    // compile-time tile id
            const int local = ((r & 1) << 8) + tid;  // 0..511 within tile
            const int row = local >> 2, c = local & 3;
            const __nv_bfloat16* src =
                (t == 0) ? Ah : (t == 1) ? Al : (t == 2) ? Bh : Bl;
            const int rbase = (t < 2) ? m0 : n0;
            CPA(sb + t * G_TILE + row * 80 + c * 16,
                src + (size_t)(rbase + row) * K + kk + c * 8);
        }
        CPC();
    };

    issue(0);
    for (int chunk = 0; chunk < kch; ++chunk) {
        CPW0();
        __syncthreads();
        if (chunk + 1 < kch) issue(chunk + 1);
        const uint32_t sb = uS + (chunk & 1) * G_STAGE;
        const uint32_t bAh = sb, bAl = sb + G_TILE;
        const uint32_t bBh = sb + 2 * G_TILE, bBl = sb + 3 * G_TILE;
#pragma unroll
        for (int ks = 0; ks < 2; ks++) {
            uint32_t ah[2][4], al[2][4];
#pragma unroll
            for (int mt = 0; mt < 2; mt++) {
                int row = wm * 32 + mt * 16 + (lane & 15);
                int col = ks * 16 + ((lane >> 4) << 3);
                ldsm4(ah[mt], bAh + (row * 40 + col) * 2);
                ldsm4(al[mt], bAl + (row * 40 + col) * 2);
            }
#pragma unroll
            for (int np = 0; np < 4; np++) {
                uint32_t bh4[4], bl4[4];
                int n = wn * 64 + np * 16 + ((lane >> 4) << 3) + (lane & 7);
                int k = ks * 16 + (((lane >> 3) & 1) << 3);
                ldsm4(bh4, bBh + (n * 40 + k) * 2);
                ldsm4(bl4, bBl + (n * 40 + k) * 2);
#pragma unroll
                for (int mt = 0; mt < 2; mt++) {
                    mma16816(acc[mt][2 * np], ah[mt], bh4[0], bh4[1]);
                    mma16816(acc[mt][2 * np + 1], ah[mt], bh4[2], bh4[3]);
                    mma16816(acc[mt][2 * np], ah[mt], bl4[0], bl4[1]);
                    mma16816(acc[mt][2 * np + 1], ah[mt], bl4[2], bl4[3]);
                    mma16816(acc[mt][2 * np], al[mt], bh4[0], bh4[1]);
                    mma16816(acc[mt][2 * np + 1], al[mt], bh4[2], bh4[3]);
                }
            }
        }
        __syncthreads();
    }

    if (MODE == 0) {
#pragma unroll
        for (int mt = 0; mt < 2; mt++) {
            int r0 = m0 + wm * 32 + mt * 16 + (lane >> 2);
#pragma unroll
            for (int nt = 0; nt < 8; nt++) {
                int c = n0 + wn * 64 + nt * 8 + ((lane & 3) << 1);
                float b0 = bias[c], b1 = bias[c + 1];
                *(float2*)&C[(size_t)r0 * N + c] =
                    make_float2(acc[mt][nt][0] + b0, acc[mt][nt][1] + b1);
                *(float2*)&C[(size_t)(r0 + 8) * N + c] =
                    make_float2(acc[mt][nt][2] + b0, acc[mt][nt][3] + b1);
            }
        }
    } else {
        // fused QKV epilogue: bias, (Q-only) scale, split hi/lo, per-head layout
#pragma unroll
        for (int nt = 0; nt < 8; nt++) {
            int c = n0 + wn * 64 + nt * 8 + ((lane & 3) << 1);
            int sel = c >> 10;        // 0=Q 1=K 2=V (warp-uniform)
            int cc = c & 1023;
            int h = cc >> 6, d = cc & 63;
            float scl = (sel == 0) ? QSCALE : 1.0f;
            __nv_bfloat16* dh = (sel == 0) ? g_qh : (sel == 1) ? g_kh : g_vh;
            __nv_bfloat16* dl = (sel == 0) ? g_ql : (sel == 1) ? g_kl : g_vl;
            float b0 = bias[c], b1 = bias[c + 1];
#pragma unroll
            for (int mt = 0; mt < 2; mt++) {
                int r0 = m0 + wm * 32 + mt * 16 + (lane >> 2);
#pragma unroll
                for (int half = 0; half < 2; half++) {
                    int r = r0 + half * 8;
                    float v0 = (acc[mt][nt][2 * half] + b0) * scl;
                    float v1 = (acc[mt][nt][2 * half + 1] + b1) * scl;
                    __nv_bfloat162 hi, lo;
                    split2(v0, v1, hi, lo);
                    size_t o = ((size_t)h * LQ + r) * 64 + d;
                    *(__nv_bfloat162*)&dh[o] = hi;
                    *(__nv_bfloat162*)&dl[o] = lo;
                }
            }
        }
    }
}

// ---------------------------------------------------------------------------
// HMMA flash attention, causal, base-2 online softmax.
// 128 threads (4 warps x 16 q-rows = 64-row q-tile) per head.
// K/V hi/lo tiles 64x64 bf16 (stride 72), 2-stage cp.async pipeline.
// Q fragments loaded directly from gmem. Epilogue writes bf16 hi/lo.
// ---------------------------------------------------------------------------
#define FT_ST 72
#define FT_TILE (64 * FT_ST * 2)   // 9216
#define FT_STAGE (4 * FT_TILE)     // 36864
#define FT_SMEM (2 * FT_STAGE)     // 73728

__global__ __launch_bounds__(128)
void flash_mma() {
    const int h = blockIdx.y;
    const int qt = (int)gridDim.x - 1 - (int)blockIdx.x; // heavy tiles first
    const int tid = threadIdx.x, lane = tid & 31, wid = tid >> 5;
    extern __shared__ __align__(16) char sm[];
    const uint32_t u0 = (uint32_t)__cvta_generic_to_shared(sm);
    const size_t hbase = (size_t)h * LQ * HDIM;

    // ---- Q fragments straight from gmem ----
    const int qrow = qt * 64 + wid * 16 + (lane >> 2);
    uint32_t qh[4][4], ql[4][4];
#pragma unroll
    for (int ks = 0; ks < 4; ks++) {
        int col = ks * 16 + ((lane & 3) << 1);
        size_t b00 = hbase + (size_t)qrow * 64 + col;
        qh[ks][0] = *(const uint32_t*)&g_qh[b00];
        qh[ks][1] = *(const uint32_t*)&g_qh[b00 + 8 * 64];
        qh[ks][2] = *(const uint32_t*)&g_qh[b00 + 8];
        qh[ks][3] = *(const uint32_t*)&g_qh[b00 + 8 * 64 + 8];
        ql[ks][0] = *(const uint32_t*)&g_ql[b00];
        ql[ks][1] = *(const uint32_t*)&g_ql[b00 + 8 * 64];
        ql[ks][2] = *(const uint32_t*)&g_ql[b00 + 8];
        ql[ks][3] = *(const uint32_t*)&g_ql[b00 + 8 * 64 + 8];
    }

    auto issue = [&](int kt) {
        const uint32_t sb = u0 + (kt & 1) * FT_STAGE;
#pragma unroll
        for (int r = 0; r < 16; r++) {
            const int t = r >> 2;                    // tile: Kh,Kl,Vh,Vl
            const int local = ((r & 3) << 7) + tid;  // 0..511
            const int row = local >> 3, c = local & 7;
            const __nv_bfloat16* src =
                (t == 0) ? g_kh : (t == 1) ? g_kl : (t == 2) ? g_vh : g_vl;
            CPA(sb + t * FT_TILE + row * (FT_ST * 2) + c * 16,
                src + hbase + (size_t)(kt * 64 + row) * 64 + c * 8);
        }
        CPC();
    };

    float o[8][4] = {};
    float m0 = -1e30f, m1 = -1e30f, l0 = 0.f, l1 = 0.f;
    const int grow0 = qrow;

    issue(0);
    for (int kt = 0; kt <= qt; ++kt) {
        CPW0();
        __syncthreads();
        if (kt < qt) issue(kt + 1);
        const uint32_t sb = u0 + (kt & 1) * FT_STAGE;
        const uint32_t uKh = sb, uKl = sb + FT_TILE;
        const uint32_t uVh = sb + 2 * FT_TILE, uVl = sb + 3 * FT_TILE;

        // ---- S = Q K^T (3 split passes) ----
        float s[8][4] = {};
#pragma unroll
        for (int pass = 0; pass < 3; ++pass) {
            const uint32_t(*qa)[4] = (pass < 2) ? qh : ql;
            const uint32_t kb = (pass == 1) ? uKl : uKh;
#pragma unroll
            for (int ks = 0; ks < 4; ks++) {
#pragma unroll
                for (int np = 0; np < 4; np++) {
                    uint32_t b4[4];
                    int n = np * 16 + ((lane >> 4) << 3) + (lane & 7);
                    int k = ks * 16 + (((lane >> 3) & 1) << 3);
                    ldsm4(b4, kb + (n * FT_ST + k) * 2);
                    mma16816(s[2 * np], qa[ks], b4[0], b4[1]);
                    mma16816(s[2 * np + 1], qa[ks], b4[2], b4[3]);
                }
            }
        }

        if (kt == qt) {  // causal mask on diagonal tile
#pragma unroll
            for (int nt = 0; nt < 8; nt++) {
                int c0 = kt * 64 + nt * 8 + ((lane & 3) << 1);
                if (c0 > grow0) s[nt][0] = -1e30f;
                if (c0 + 1 > grow0) s[nt][1] = -1e30f;
                if (c0 > grow0 + 8) s[nt][2] = -1e30f;
                if (c0 + 1 > grow0 + 8) s[nt][3] = -1e30f;
            }
        }

        // ---- online softmax (base-2) ----
        float mx0 = -1e30f, mx1 = -1e30f;
#pragma unroll
        for (int nt = 0; nt < 8; nt++) {
            mx0 = fmaxf(mx0, fmaxf(s[nt][0], s[nt][1]));
            mx1 = fmaxf(mx1, fmaxf(s[nt][2], s[nt][3]));
        }
        mx0 = fmaxf(mx0, __shfl_xor_sync(0xffffffffu, mx0, 1));
        mx0 = fmaxf(mx0, __shfl_xor_sync(0xffffffffu, mx0, 2));
        mx1 = fmaxf(mx1, __shfl_xor_sync(0xffffffffu, mx1, 1));
        mx1 = fmaxf(mx1, __shfl_xor_sync(0xffffffffu, mx1, 2));
        float mn0 = fmaxf(m0, mx0), mn1 = fmaxf(m1, mx1);
        float corr0 = ex2f(m0 - mn0), corr1 = ex2f(m1 - mn1);
        m0 = mn0; m1 = mn1;
        float ps0 = 0.f, ps1 = 0.f;
#pragma unroll
        for (int nt = 0; nt < 8; nt++) {
            s[nt][0] = ex2f(s[nt][0] - mn0);
            s[nt][1] = ex2f(s[nt][1] - mn0);
            s[nt][2] = ex2f(s[nt][2] - mn1);
            s[nt][3] = ex2f(s[nt][3] - mn1);
            ps0 += s[nt][0] + s[nt][1];
            ps1 += s[nt][2] + s[nt][3];
        }
        ps0 += __shfl_xor_sync(0xffffffffu, ps0, 1);
        ps0 += __shfl_xor_sync(0xffffffffu, ps0, 2);
        ps1 += __shfl_xor_sync(0xffffffffu, ps1, 1);
        ps1 += __shfl_xor_sync(0xffffffffu, ps1, 2);
        l0 = l0 * corr0 + ps0;
        l1 = l1 * corr1 + ps1;
#pragma unroll
        for (int nt = 0; nt < 8; nt++) {
            o[nt][0] *= corr0; o[nt][1] *= corr0;
            o[nt][2] *= corr1; o[nt][3] *= corr1;
        }

        // ---- O += P V (3 split passes) ----
#pragma unroll
        for (int pass = 0; pass < 3; ++pass) {
            const uint32_t vb = (pass == 1) ? uVl : uVh;
#pragma unroll
            for (int ks = 0; ks < 4; ks++) {
                uint32_t a[4];
                if (pass < 2) {
                    a[0] = packbf(s[2 * ks][0], s[2 * ks][1]);
                    a[1] = packbf(s[2 * ks][2], s[2 * ks][3]);
                    a[2] = packbf(s[2 * ks + 1][0], s[2 * ks + 1][1]);
                    a[3] = packbf(s[2 * ks + 1][2], s[2 * ks + 1][3]);
                } else {
                    a[0] = packbf(lowres(s[2 * ks][0]), lowres(s[2 * ks][1]));
                    a[1] = packbf(lowres(s[2 * ks][2]), lowres(s[2 * ks][3]));
                    a[2] = packbf(lowres(s[2 * ks + 1][0]), lowres(s[2 * ks + 1][1]));
                    a[3] = packbf(lowres(s[2 * ks + 1][2]), lowres(s[2 * ks + 1][3]));
                }
#pragma unroll
                for (int np = 0; np < 4; np++) {
                    uint32_t b4[4];
                    int row = ks * 16 + ((lane >> 3) & 1) * 8 + (lane & 7);
                    int dc = np * 16 + ((lane >> 4) << 3);
                    ldsm4t(b4, vb + (row * FT_ST + dc) * 2);
                    mma16816(o[2 * np], a, b4[0], b4[1]);
                    mma16816(o[2 * np + 1], a, b4[2], b4[3]);
                }
            }
        }
    }

    // ---- epilogue: normalize, split hi/lo, write [L][C] bf16 ----
    float inv0 = 1.f / l0, inv1 = 1.f / l1;
#pragma unroll
    for (int nt = 0; nt < 8; nt++) {
        int c = h * 64 + nt * 8 + ((lane & 3) << 1);
        __nv_bfloat162 hi, lo;
        split2(o[nt][0] * inv0, o[nt][1] * inv0, hi, lo);
        size_t off0 = (size_t)grow0 * CDIM + c;
        *(__nv_bfloat162*)&g_ah[off0] = hi;
        *(__nv_bfloat162*)&g_al[off0] = lo;
        split2(o[nt][2] * inv1, o[nt][3] * inv1, hi, lo);
        size_t off1 = (size_t)(grow0 + 8) * CDIM + c;
        *(__nv_bfloat162*)&g_ah[off1] = hi;
        *(__nv_bfloat162*)&g_al[off1] = lo;
    }
}

// ---------------------------------------------------------------------------
// Launch
// ---------------------------------------------------------------------------
extern "C" void kernel_launch(void* const* d_in, const int* in_sizes, int n_in,
                              void* d_out, int out_size) {
    (void)in_sizes; (void)n_in; (void)out_size;
    const float* x = (const float*)d_in[0];
    const float* Wqkv = (const float*)d_in[1];
    const float* bqkv = (const float*)d_in[2];
    const float* Wout = (const float*)d_in[3];
    const float* bout = (const float*)d_in[4];
    float* out = (float*)d_out;

    __nv_bfloat16 *xh, *xl, *ah, *al, *wqh, *wql, *woh, *wol;
    cudaGetSymbolAddress((void**)&xh, g_xh);
    cudaGetSymbolAddress((void**)&xl, g_xl);
    cudaGetSymbolAddress((void**)&ah, g_ah);
    cudaGetSymbolAddress((void**)&al, g_al);
    cudaGetSymbolAddress((void**)&wqh, g_wqh);
    cudaGetSymbolAddress((void**)&wql, g_wql);
    cudaGetSymbolAddress((void**)&woh, g_woh);
    cudaGetSymbolAddress((void**)&wol, g_wol);

    static int attr_set = 0;
    if (!attr_set) {
        cudaFuncSetAttribute(gemm3<0>, cudaFuncAttributeMaxDynamicSharedMemorySize, G_SMEM);
        cudaFuncSetAttribute(gemm3<1>, cudaFuncAttributeMaxDynamicSharedMemorySize, G_SMEM);
        cudaFuncSetAttribute(flash_mma, cudaFuncAttributeMaxDynamicSharedMemorySize, FT_SMEM);
        attr_set = 1;
    }

    // prep: split X, transpose-split weights
    split_kernel<<<(LQ * CDIM) / 256, 256>>>(x, xh, xl, LQ * CDIM);
    tsplit_kernel<<<dim3(C3 / 32, CDIM / 32), 256>>>(Wqkv, wqh, wql, CDIM, C3);
    tsplit_kernel<<<dim3(CDIM / 32, CDIM / 32), 256>>>(Wout, woh, wol, CDIM, CDIM);

    // 1) QKV projection with fused per-head bf16 hi/lo epilogue
    gemm3<1><<<dim3(C3 / 128, LQ / 128), 256, G_SMEM>>>(
        xh, xl, wqh, wql, bqkv, nullptr, LQ, C3, CDIM);

    // 2) causal flash attention (writes bf16 hi/lo attn output)
    flash_mma<<<dim3(LQ / 64, NHEADS), 128, FT_SMEM>>>();

    // 3) output projection
    gemm3<0><<<dim3(CDIM / 128, LQ / 128), 256, G_SMEM>>>(
        ah, al, woh, wol, bout, out, LQ, CDIM, CDIM);
}